// round 6
// baseline (speedup 1.0000x reference)
#include <cuda_runtime.h>

// Dilation 9x9 (sliding-window max), input (16, 1024, 1024, 1) fp32.
// Separable: vertical 9-max in registers (ring of float4), horizontal 9-max
// via shared row + pairwise-tree. One fused streaming kernel.

#define IMG_W 1024
#define IMG_H 1024
#define BATCH 16
#define RAD 4          // (9-1)/2
#define TY 54          // output rows per block (multiple of 9)
#define NTHR 256       // threads per block; each owns 4 consecutive columns

__device__ __forceinline__ float4 fmax4(float4 a, float4 b) {
    return make_float4(fmaxf(a.x, b.x), fmaxf(a.y, b.y),
                       fmaxf(a.z, b.z), fmaxf(a.w, b.w));
}

__device__ __forceinline__ float4 neg_inf4() {
    float ninf = __int_as_float(0xff800000);
    return make_float4(ninf, ninf, ninf, ninf);
}

__global__ __launch_bounds__(NTHR, 3)
void dilate9x9_kernel(const float* __restrict__ in, float* __restrict__ out) {
    __shared__ __align__(16) float vrow[IMG_W + 2 * RAD];  // 1032 floats

    const int t = threadIdx.x;          // 0..255
    const int x = t << 2;               // owned columns x..x+3
    const int b = blockIdx.y;
    const int y0 = blockIdx.x * TY;
    const int yend = min(y0 + TY, IMG_H);

    const float* img = in + (size_t)b * IMG_H * IMG_W;
    float* oimg = out + (size_t)b * IMG_H * IMG_W;

    // Horizontal halo cells: columns <0 and >=W are -inf, written once.
    if (t < RAD) {
        float ninf = __int_as_float(0xff800000);
        vrow[t] = ninf;                       // indices 0..3
        vrow[IMG_W + RAD + t] = ninf;         // indices 1028..1031
    }

    // Vertical ring: ring[j] holds input row (y - RAD + j) for current y.
    float4 ring[9];
#pragma unroll
    for (int k = 0; k < 8; ++k) {
        int r = y0 - RAD + k;
        ring[k] = (r >= 0 && r < IMG_H)
                      ? *reinterpret_cast<const float4*>(img + (size_t)r * IMG_W + x)
                      : neg_inf4();
    }
    ring[8] = neg_inf4();

    for (int yy = 0; yy < TY; yy += 9) {
#pragma unroll
        for (int k = 0; k < 9; ++k) {
            int y = y0 + yy + k;
            if (y >= yend) break;  // uniform across block (y doesn't depend on t)

            // Load the newest row (y + RAD) into the static ring slot.
            {
                int r = y + RAD;
                float4 nv = (r < IMG_H)
                                ? *reinterpret_cast<const float4*>(img + (size_t)r * IMG_W + x)
                                : neg_inf4();
                ring[(8 + k) % 9] = nv;  // compile-time index (yy % 9 == 0)
            }

            // Vertical max over the 9 ring rows (order-independent).
            float4 vm = ring[0];
#pragma unroll
            for (int j = 1; j < 9; ++j) vm = fmax4(vm, ring[j]);

            // Publish column-max row (offset by RAD; halos stay -inf).
            *reinterpret_cast<float4*>(&vrow[RAD + x]) = vm;
            __syncthreads();

            // Horizontal pass: outputs x..x+3 need vrow[x .. x+11] (aligned).
            float4 a = *reinterpret_cast<const float4*>(&vrow[x]);
            float4 bb = *reinterpret_cast<const float4*>(&vrow[x + 4]);
            float4 c = *reinterpret_cast<const float4*>(&vrow[x + 8]);

            float v[12] = {a.x, a.y, a.z, a.w, bb.x, bb.y, bb.z, bb.w,
                           c.x, c.y, c.z, c.w};
            float m2[10], m4[8], m8[4];
#pragma unroll
            for (int i = 0; i < 10; ++i) m2[i] = fmaxf(v[i], v[i + 1]);
#pragma unroll
            for (int i = 0; i < 8; ++i) m4[i] = fmaxf(m2[i], m2[i + 2]);
#pragma unroll
            for (int i = 0; i < 4; ++i) m8[i] = fmaxf(m4[i], m4[i + 4]);

            float4 o;
            o.x = fmaxf(m8[0], v[8]);
            o.y = fmaxf(m8[1], v[9]);
            o.z = fmaxf(m8[2], v[10]);
            o.w = fmaxf(m8[3], v[11]);

            *reinterpret_cast<float4*>(oimg + (size_t)y * IMG_W + x) = o;

            __syncthreads();  // protect vrow before next iteration's write
        }
    }
}

extern "C" void kernel_launch(void* const* d_in, const int* in_sizes, int n_in,
                              void* d_out, int out_size) {
    const float* in = (const float*)d_in[0];
    float* out = (float*)d_out;
    dim3 grid((IMG_H + TY - 1) / TY, BATCH);  // 19 x 16 = 304 blocks
    dilate9x9_kernel<<<grid, NTHR>>>(in, out);
}

// round 10
// speedup vs baseline: 1.5571x; 1.5571x over previous
#include <cuda_runtime.h>

// Dilation 9x9 (sliding-window max), (16,1024,1024,1) fp32.
// Separable max, grouped 4 rows/iter (MLP=4), van Herk vertical
// (suffix/prefix segments), double-buffered smem horizontal pass with ONE
// __syncthreads per group, next-group loads prefetched before the sync.

#define IMG_W 1024
#define IMG_H 1024
#define BATCH 16
#define RAD 4
#define TY 32                 // output rows per block (1024 % 32 == 0)
#define G 4                   // rows per group
#define NGROUPS (TY / G)      // 8
#define NTHR 256              // thread t owns columns 4t..4t+3
#define ROWF (IMG_W + 2 * RAD)  // 1032 floats per smem row

__device__ __forceinline__ float4 fmax4(float4 a, float4 b) {
    return make_float4(fmaxf(a.x, b.x), fmaxf(a.y, b.y),
                       fmaxf(a.z, b.z), fmaxf(a.w, b.w));
}

__device__ __forceinline__ float4 neg_inf4() {
    float ninf = __int_as_float(0xff800000);
    return make_float4(ninf, ninf, ninf, ninf);
}

__global__ __launch_bounds__(NTHR, 3)
void dilate9x9_kernel(const float* __restrict__ in, float* __restrict__ out) {
    __shared__ __align__(16) float buf[2][G][ROWF];  // 33 KB

    const int t = threadIdx.x;
    const int x = t << 2;
    const int b = blockIdx.y;
    const int y0 = blockIdx.x * TY;

    const float* img = in + (size_t)b * IMG_H * IMG_W;
    float* oimg = out + (size_t)b * IMG_H * IMG_W;

    // -inf halo cells: 2 buffers x 4 rows x 8 cells = 64, written once.
    if (t < 64) {
        int bi = t >> 5;            // buffer 0/1
        int r = (t >> 3) & 3;       // row 0..3
        int c = t & 7;              // halo cell 0..7
        int col = (c < RAD) ? c : (IMG_W + c);  // 0..3 or 1028..1031
        buf[bi][r][col] = __int_as_float(0xff800000);
    }

    auto ld = [&](int r) -> float4 {
        return (r >= 0 && r < IMG_H)
                   ? *reinterpret_cast<const float4*>(img + (size_t)r * IMG_W + x)
                   : neg_inf4();
    };

    // Segment state (van Herk, segment = 4 rows):
    //   sB[i] = max(rows y-4+i .. y-1)   (suffixes of segment before current)
    //   sC[i] = max(rows y+i  .. y+3)    (suffixes of current segment; sC0 = all)
    //   d0..d3 = raw rows y+4 .. y+7     (next segment, prefix built on the fly)
    float4 sB0, sB1, sB2, sB3, sC0, sC1, sC2, sC3, d0, d1, d2, d3;
    {
        float4 b0 = ld(y0 - 4), b1 = ld(y0 - 3), b2 = ld(y0 - 2), b3 = ld(y0 - 1);
        float4 c0 = ld(y0), c1 = ld(y0 + 1), c2 = ld(y0 + 2), c3 = ld(y0 + 3);
        d0 = ld(y0 + 4); d1 = ld(y0 + 5); d2 = ld(y0 + 6); d3 = ld(y0 + 7);
        sB3 = b3; sB2 = fmax4(b2, sB3); sB1 = fmax4(b1, sB2); sB0 = fmax4(b0, sB1);
        sC3 = c3; sC2 = fmax4(c2, sC3); sC1 = fmax4(c1, sC2); sC0 = fmax4(c0, sC1);
    }

#pragma unroll
    for (int g = 0; g < NGROUPS; ++g) {
        const int y = y0 + g * G;
        float* mybuf = &buf[g & 1][0][0];

        // Vertical 9-max for output rows y..y+3:
        //   vm(i) = max( sB[i], sC[0], prefixD[i] )   — (4-i) + 4 + (i+1) = 9 rows
        float4 p = d0;
        *reinterpret_cast<float4*>(mybuf + 0 * ROWF + RAD + x) =
            fmax4(fmax4(sB0, sC0), p);
        p = fmax4(p, d1);
        *reinterpret_cast<float4*>(mybuf + 1 * ROWF + RAD + x) =
            fmax4(fmax4(sB1, sC0), p);
        p = fmax4(p, d2);
        *reinterpret_cast<float4*>(mybuf + 2 * ROWF + RAD + x) =
            fmax4(fmax4(sB2, sC0), p);
        p = fmax4(p, d3);
        *reinterpret_cast<float4*>(mybuf + 3 * ROWF + RAD + x) =
            fmax4(fmax4(sB3, sC0), p);

        // Rotate segments: B <- C, C <- suffixes(D).
        sB0 = sC0; sB1 = sC1; sB2 = sC2; sB3 = sC3;
        sC3 = d3; sC2 = fmax4(d2, sC3); sC1 = fmax4(d1, sC2); sC0 = fmax4(d0, sC1);

        // Prefetch next group's segment BEFORE the barrier so DRAM latency
        // overlaps the sync + horizontal pass. (Skip on last group.)
        if (g + 1 < NGROUPS) {
            d0 = ld(y + 8); d1 = ld(y + 9); d2 = ld(y + 10); d3 = ld(y + 11);
        }

        // Single barrier per group. Double buffering makes the second barrier
        // unnecessary: group g+2 writes this buffer only after the sync of
        // group g+1, which orders it after all of group g's reads.
        __syncthreads();

        // Horizontal 9-max for the 4 rows, pairwise tree (26 fmax / float4).
#pragma unroll
        for (int r = 0; r < G; ++r) {
            const float* rp = mybuf + r * ROWF + x;
            float4 a = *reinterpret_cast<const float4*>(rp);
            float4 e = *reinterpret_cast<const float4*>(rp + 4);
            float4 c = *reinterpret_cast<const float4*>(rp + 8);

            float v[12] = {a.x, a.y, a.z, a.w, e.x, e.y, e.z, e.w,
                           c.x, c.y, c.z, c.w};
            float m2[10], m4[8], m8[4];
#pragma unroll
            for (int i = 0; i < 10; ++i) m2[i] = fmaxf(v[i], v[i + 1]);
#pragma unroll
            for (int i = 0; i < 8; ++i) m4[i] = fmaxf(m2[i], m2[i + 2]);
#pragma unroll
            for (int i = 0; i < 4; ++i) m8[i] = fmaxf(m4[i], m4[i + 4]);

            float4 o;
            o.x = fmaxf(m8[0], v[8]);
            o.y = fmaxf(m8[1], v[9]);
            o.z = fmaxf(m8[2], v[10]);
            o.w = fmaxf(m8[3], v[11]);

            *reinterpret_cast<float4*>(oimg + (size_t)(y + r) * IMG_W + x) = o;
        }
    }
}

extern "C" void kernel_launch(void* const* d_in, const int* in_sizes, int n_in,
                              void* d_out, int out_size) {
    const float* in = (const float*)d_in[0];
    float* out = (float*)d_out;
    dim3 grid(IMG_H / TY, BATCH);  // 32 x 16 = 512 blocks
    dilate9x9_kernel<<<grid, NTHR>>>(in, out);
}